// round 10
// baseline (speedup 1.0000x reference)
#include <cuda_runtime.h>
#include <cuda_bf16.h>
#include <cstdint>

// DifferentiableExtrusion: B=4, N=32 polygons, P=32 edges, V=96 grid.
// out[b,z,y,x] = (z < hv[b]) * max_{n valid} sigmoid(-100 * sdf_n(x,y))
//
// R8 structure: 1 CTA = 1 grid row (96 points) of 1 batch.
//  * block (32,8): 8 polygon groups; thread handles 3 points x=tx,tx+32,tx+64
//    -> per-edge LDS amortized over 3 points, row-uniform terms shared.
//  * t = sat(fma(px,c1,c0)) with c0,c1 precomputed per (row,edge).
//    Parity path (ix sentinel) kept bit-identical to validated R7 kernel.
//  * 384 CTAs, launch_bounds(256,4) -> ~2-3 CTAs/SM, high occupancy.

#define V 96
#define NPOLY 32
#define PEDGE 32
#define NEDGES (NPOLY * PEDGE)   // 1024
#define SHARPNESS 100.0f
#define EPS 1e-8f
#define FLT_BIG 3.402823466e38f
#define DEEP_IN2 0.01f           // (0.1)^2 : sigmoid(100*0.1) = 1 - 4.5e-5

__global__ __launch_bounds__(256, 4)
void extrusion_kernel(const float* __restrict__ polygons,     // [B,N,P,2]
                      const float* __restrict__ attributes,   // [B,8]
                      const float* __restrict__ validity,     // [B,N]
                      float* __restrict__ out)                // [B,V,V,V]
{
    __shared__ float4 sEA[NEDGES];       // x0, ex, ey, c1
    __shared__ float4 sEB[NEDGES];       // c0, vy, ix, --
    __shared__ float2 sRed[8][3][32];    // (negmax, posmin) per (group, chunk, lane)
    __shared__ int    sList[NPOLY];
    __shared__ int    sNv;

    const int b  = blockIdx.y;
    const int gy = blockIdx.x;           // this CTA's grid row
    const int tx = threadIdx.x;          // 32 lanes
    const int ty = threadIdx.y;          // 8 polygon groups (warp id)
    const int tid = tx + 32 * ty;

    const float inv_vm1 = 1.0f / (float)(V - 1);
    const float py = (float)gy * inv_vm1;

    // ---- per-(row,edge) precompute into shared ----
    const float* pb = polygons + (size_t)b * NEDGES * 2;
    #pragma unroll
    for (int e = tid; e < NEDGES; e += 256) {
        int n = e >> 5;
        int p = e & 31;
        int p1 = (p + 1) & 31;
        float x0 = pb[(n * PEDGE + p ) * 2 + 0];
        float y0 = pb[(n * PEDGE + p ) * 2 + 1];
        float x1 = pb[(n * PEDGE + p1) * 2 + 0];
        float y1 = pb[(n * PEDGE + p1) * 2 + 1];
        float ex = x1 - x0;
        float ey = y1 - y0;
        float inv_esq = 1.0f / (ex * ex + ey * ey + EPS);
        float inv_dy  = 1.0f / (ey + EPS);
        float vy = py - y0;
        float cc1 = ex * inv_esq;
        float cc0 = (vy * ey - x0 * ex) * inv_esq;
        bool  yc = (y0 <= py) != (y1 <= py);
        float ix = yc ? (x0 + ex * (vy * inv_dy)) : -1.0f;   // sentinel: never > px
        sEA[e] = make_float4(x0, ex, ey, cc1);
        sEB[e] = make_float4(cc0, vy, ix, 0.0f);
    }
    if (tid < 32) {
        bool v = (validity[b * NPOLY + tid] >= 0.5f);
        unsigned m = __ballot_sync(0xffffffffu, v);
        if (v) sList[__popc(m & ((1u << tid) - 1u))] = tid;
        if (tid == 0) sNv = __popc(m);
    }
    __syncthreads();
    const int nv = sNv;

    // ---- 3 points of this row per thread ----
    const float px0 = (float)(tx     ) * inv_vm1;
    const float px1 = (float)(tx + 32) * inv_vm1;
    const float px2 = (float)(tx + 64) * inv_vm1;

    float ng0 = -1.0f, ng1 = -1.0f, ng2 = -1.0f;       // max d^2 inside
    float ps0 = FLT_BIG, ps1 = FLT_BIG, ps2 = FLT_BIG; // min d^2 outside

    for (int i = ty; i < nv; i += 8) {
        const int base = sList[i] << 5;
        float m0 = FLT_BIG, m1 = FLT_BIG, m2 = FLT_BIG;
        int   k0 = 0, k1 = 0, k2 = 0;
        #pragma unroll 4
        for (int p = 0; p < PEDGE; ++p) {
            float4 a  = sEA[base + p];     // x0, ex, ey, c1
            float4 bb = sEB[base + p];     // c0, vy, ix
            {   // point 0
                float vx = px0 - a.x;
                float t  = __saturatef(fmaf(px0, a.w, bb.x));
                float dx = fmaf(-t, a.y, vx);
                float dy = fmaf(-t, a.z, bb.y);
                m0 = fminf(m0, fmaf(dy, dy, dx * dx));
                k0 += (bb.z > px0);
            }
            {   // point 1
                float vx = px1 - a.x;
                float t  = __saturatef(fmaf(px1, a.w, bb.x));
                float dx = fmaf(-t, a.y, vx);
                float dy = fmaf(-t, a.z, bb.y);
                m1 = fminf(m1, fmaf(dy, dy, dx * dx));
                k1 += (bb.z > px1);
            }
            {   // point 2
                float vx = px2 - a.x;
                float t  = __saturatef(fmaf(px2, a.w, bb.x));
                float dx = fmaf(-t, a.y, vx);
                float dy = fmaf(-t, a.z, bb.y);
                m2 = fminf(m2, fmaf(dy, dy, dx * dx));
                k2 += (bb.z > px2);
            }
        }
        if (k0 & 1) ng0 = fmaxf(ng0, m0); else ps0 = fminf(ps0, m0);
        if (k1 & 1) ng1 = fmaxf(ng1, m1); else ps1 = fminf(ps1, m1);
        if (k2 & 1) ng2 = fmaxf(ng2, m2); else ps2 = fminf(ps2, m2);
        // warp-uniform early exit: all 96 row-points deep inside
        if (__all_sync(0xffffffffu,
                       (ng0 > DEEP_IN2) & (ng1 > DEEP_IN2) & (ng2 > DEEP_IN2)))
            break;
    }

    // ---- combine the 8 polygon groups ----
    sRed[ty][0][tx] = make_float2(ng0, ps0);
    sRed[ty][1][tx] = make_float2(ng1, ps1);
    sRed[ty][2][tx] = make_float2(ng2, ps2);
    __syncthreads();

    float mres[3];
    #pragma unroll
    for (int c = 0; c < 3; ++c) {
        float ng = -1.0f, ps = FLT_BIG;
        #pragma unroll
        for (int g = 0; g < 8; ++g) {
            float2 r = sRed[g][c][tx];
            ng = fmaxf(ng, r.x);
            ps = fminf(ps, r.y);
        }
        bool inside = (ng >= 0.0f);
        float d   = sqrtf(inside ? ng : ps);
        float sdf = inside ? -d : d;
        // nv==0: ps=FLT_BIG -> exp -> inf -> m = 0  (matches ref)
        mres[c] = 1.0f / (1.0f + __expf(SHARPNESS * sdf));
    }

    // ---- fused z-extrusion: 12 z-slices per group, full row, coalesced ----
    float hraw = __ldg(&attributes[b * 8]);
    float hv = fminf(fmaxf(rintf(__saturatef(hraw) * (float)V), 1.0f), (float)V);
    int hvi = (int)hv;

    float* ob = out + (size_t)b * V * V * V + (size_t)gy * V;
    const int z0 = ty * 12;
    #pragma unroll 4
    for (int z = z0; z < z0 + 12; ++z) {
        float* row = ob + (size_t)z * (V * V);
        bool on = (z < hvi);
        row[tx     ] = on ? mres[0] : 0.0f;
        row[tx + 32] = on ? mres[1] : 0.0f;
        row[tx + 64] = on ? mres[2] : 0.0f;
    }
}

extern "C" void kernel_launch(void* const* d_in, const int* in_sizes, int n_in,
                              void* d_out, int out_size)
{
    const float* polygons   = (const float*)d_in[0];  // [4,32,32,2]
    const float* attributes = (const float*)d_in[1];  // [4,8]
    const float* validity   = (const float*)d_in[2];  // [4,32]
    float* out = (float*)d_out;                       // [4,96,96,96]

    dim3 grid(V, 4);             // (96, 4) = 384 CTAs, one row each
    dim3 block(32, 8);           // 256 threads, 8 polygon groups
    extrusion_kernel<<<grid, block>>>(polygons, attributes, validity, out);
}